// round 10
// baseline (speedup 1.0000x reference)
#include <cuda_runtime.h>
#include <math_constants.h>

#define N   512
#define NT  256
#define NW  (NT / 32)
#define FULLMASK 0xffffffffu
#define ARR_CAP (3 * N)

typedef long long ll;
typedef unsigned long long ull;

#define LL_INF 0x7fffffffffffffffLL
#define SIGNF  0x8000000000000000ULL
// 2^50 fixed-point scale: total quantization error << optimum uniqueness margin.
#define SCALE_D 1125899906842624.0

// 512x512 int64 cost matrix (2 MB) — static device scratch (no allocs).
__device__ ll g_icost[N * N];

__device__ __forceinline__ ull bias(ll x) { return (ull)x ^ SIGNF; }
__device__ __forceinline__ ll  unbias(ull k) { return (ll)(k ^ SIGNF); }

// Quantized Euclidean cost from squared distance. Fast sqrt: rsqrtf seed +
// 2 double NR iterations (~2^-49 rel err; tolerance is ~2^-40 abs). Guard
// keeps tiny/zero ss exact-enough and NaN-free.
__device__ __forceinline__ ll qcost(double ss) {
    if (ss < 1e-22) return 0;
    double r = (double)rsqrtf((float)ss);
    double h = 0.5 * ss;
    r = r * (1.5 - h * r * r);
    r = r * (1.5 - h * r * r);
    return __double2ll_rn(ss * r * SCALE_D);
}

// Block-wide exact (min int64 key, payload). All NT threads call, uniform.
// One __syncthreads inside; caller double-buffers `slots`.
__device__ __forceinline__ void block_argmin(ll key, ull payload, ulonglong2* slots,
                                             ll& bk, ull& bpay)
{
    const int lane = threadIdx.x & 31;
    const int w    = threadIdx.x >> 5;
    ull bkey = bias(key);
    unsigned hi  = (unsigned)(bkey >> 32);
    unsigned lo  = (unsigned)bkey;
    unsigned whi = __reduce_min_sync(FULLMASK, hi);
    unsigned wlo = __reduce_min_sync(FULLMASK, (hi == whi) ? lo : 0xffffffffu);
    unsigned msk = __ballot_sync(FULLMASK, (hi == whi) && (lo == wlo));
    if (lane == __ffs(msk) - 1)
        slots[w] = make_ulonglong2(bkey, payload);
    __syncthreads();
    ulonglong2 a0 = slots[0], a1 = slots[1], a2 = slots[2], a3 = slots[3];
    ulonglong2 a4 = slots[4], a5 = slots[5], a6 = slots[6], a7 = slots[7];
    if (a4.x < a0.x) a0 = a4;
    if (a5.x < a1.x) a1 = a5;
    if (a6.x < a2.x) a2 = a6;
    if (a7.x < a3.x) a3 = a7;
    if (a2.x < a0.x) a0 = a2;
    if (a3.x < a1.x) a1 = a3;
    if (a1.x < a0.x) a0 = a1;
    bk   = unbias(a0.x);
    bpay = a0.y;
}

__global__ void __launch_bounds__(NT, 1)
tofu_lap_kernel(const float* __restrict__ dgm,
                const float* __restrict__ dgm_x,
                float* __restrict__ out)
{
    const int t  = threadIdx.x;       // owns columns c0 = 2t, c1 = 2t+1
    const int c0 = 2 * t, c1 = 2 * t + 1;
    const int w  = t >> 5;
    const int lane = t & 31;

    __shared__ ll         s_u[N];          // row duals (int64)
    __shared__ int        s_p[N];          // col -> matched row, -1 if free
    __shared__ int        s_way[N];        // Dijkstra parents (temp: CR row flags)
    __shared__ int        s_xrow[N];       // row -> matched col, -1 (for RT)
    __shared__ int        s_argmin[N];
    __shared__ int        s_list[2][N];    // ARR ping-pong / final free-row list
    __shared__ ulonglong2 s_slots[2][NW];  // (biased key, payload) double-buffered
    __shared__ ll         s_uslt[2][NW];   // shipped u of candidate
    __shared__ double     s_red[NW];

    // ---------------------------------------------------------------
    // Phase 0 (+ fused column reduction): int64 cost matrix and
    // per-column min/argmin in one pass. FMA/fast-sqrt allowed: the
    // fixed-point tolerance (abs err << margin) covers it.
    // ---------------------------------------------------------------
    ll v0, v1;
    {
        const double xb0 = (double)dgm_x[2 * c0], xd0 = (double)dgm_x[2 * c0 + 1];
        const double xb1 = (double)dgm_x[2 * c1], xd1 = (double)dgm_x[2 * c1 + 1];
        ll vm0 = LL_INF, vm1 = LL_INF;
        int a0 = 0, a1 = 0;
        for (int i = 0; i < N; i++) {
            const double b = (double)dgm[2 * i], d = (double)dgm[2 * i + 1];
            double db0 = b - xb0, dd0 = d - xd0;
            double db1 = b - xb1, dd1 = d - xd1;
            longlong2 cc;
            cc.x = qcost(db0 * db0 + dd0 * dd0);
            cc.y = qcost(db1 * db1 + dd1 * dd1);
            *(longlong2*)&g_icost[i * N + c0] = cc;
            if (cc.x < vm0) { vm0 = cc.x; a0 = i; }
            if (cc.y < vm1) { vm1 = cc.y; a1 = i; }
        }
        v0 = vm0; v1 = vm1;
        s_argmin[c0] = a0; s_argmin[c1] = a1;
        s_way[c0] = 0; s_way[c1] = 0;      // temp: row-claimed flags for CR
    }
    __syncthreads();

    // Greedy pre-match of unique argmin rows (tight, feasible).
    if (t == 0) {
        int cnt = 0;
        for (int i = 0; i < N; i++) s_xrow[i] = -1;
        for (int jj = 0; jj < N; jj++) {
            int r = s_argmin[jj];
            if (!s_way[r]) { s_way[r] = 1; s_p[jj] = r; s_xrow[r] = jj; }
            else           { s_p[jj] = -1; }
        }
        for (int i = 0; i < N; i++)
            if (!s_way[i]) s_list[0][cnt++] = i;
        s_argmin[0] = cnt;
    }
    __syncthreads();
    const int cnt0 = s_argmin[0];

    int pb = 0;

    // ---------------------------------------------------------------
    // Phase 1b: reduction transfer. v[j1] -= min_{j!=j1}(c[i][j]-v[j])
    // for each CR-matched row. Next-row prefetch (addresses known).
    // ---------------------------------------------------------------
    {
        longlong2 ccn = *(const longlong2*)&g_icost[c0];
        for (int i = 0; i < N; i++) {
            longlong2 cc = ccn;
            if (i + 1 < N) ccn = *(const longlong2*)&g_icost[(i + 1) * N + c0];
            const int j1 = s_xrow[i];      // broadcast LDS; uniform branch
            if (j1 < 0) continue;
            ll k0 = (c0 == j1) ? LL_INF : (cc.x - v0);
            ll k1 = (c1 == j1) ? LL_INF : (cc.y - v1);
            ll kl = (k1 < k0) ? k1 : k0;
            ll bk; ull bp;
            block_argmin(kl, 0, s_slots[pb], bk, bp); pb ^= 1;
            if (c0 == j1) v0 -= bk;
            if (c1 == j1) v1 -= bk;
        }
    }
    __syncthreads();

    // ---------------------------------------------------------------
    // Phase 1c: augmenting row reduction. Driver state fully replicated
    // across threads (uniform); only s_p / s_list writes are t0's.
    // ---------------------------------------------------------------
    int fsel, fcnt;
    {
        int p0r = s_p[c0], p1r = s_p[c1];   // register mirrors of own cols
        int kidx = 1, cntIn = cnt0, cntOut = 0;
        int insel = 0, outsel = 1, sweep = 0, iters = 0;

        if (cntIn == 0) { fsel = 1; fcnt = 0; }
        else {
            int i = s_list[0][0];
            longlong2 cc = *(const longlong2*)&g_icost[i * N + c0];
            while (true) {
                ll k0 = cc.x - v0;
                ll k1 = cc.y - v1;
                ull pay0 = ((ull)(unsigned)(p0r + 1) << 32) | (unsigned)c0;
                ull pay1 = ((ull)(unsigned)(p1r + 1) << 32) | (unsigned)c1;
                ll kl; ull pl;
                if (k1 < k0) { kl = k1; pl = pay1; } else { kl = k0; pl = pay0; }
                ll kmin; ull p1u;
                block_argmin(kl, pl, s_slots[pb], kmin, p1u); pb ^= 1;
                const int j1   = (int)(unsigned)p1u;
                const int p_j1 = (int)(unsigned)(p1u >> 32) - 1;

                // speculative: displaced-row cc (used when strict && p_j1>=0)
                longlong2 ccD;
                {
                    int pr = (p_j1 >= 0) ? p_j1 : 0;
                    ccD = *(const longlong2*)&g_icost[pr * N + c0];
                }

                ll e0 = (c0 == j1) ? LL_INF : k0;
                ll e1 = (c1 == j1) ? LL_INF : k1;
                if (e1 < e0) { kl = e1; pl = pay1; } else { kl = e0; pl = pay0; }
                ll ksub; ull p2u;
                block_argmin(kl, pl, s_slots[pb], ksub, p2u); pb ^= 1;
                const int j2   = (int)(unsigned)p2u;
                const int p_j2 = (int)(unsigned)(p2u >> 32) - 1;

                const bool strict = (kmin < ksub);
                if (strict) {
                    ll dv = ksub - kmin;
                    if      (j1 == c0) v0 -= dv;
                    else if (j1 == c1) v1 -= dv;
                }
                // uniform driver
                int jf = j1, i0;
                if (!strict && p_j1 >= 0) { jf = j2; i0 = p_j2; }
                else                      { i0 = p_j1; }
                if (t == 0) s_p[jf] = i;
                if (jf == c0) p0r = i;
                if (jf == c1) p1r = i;
                iters++;

                int nexti = -1;
                bool fromDisp = false;
                if (i0 >= 0 && strict) { nexti = i0; fromDisp = true; }
                else {
                    if (i0 >= 0) { if (t == 0) s_list[outsel][cntOut] = i0; cntOut++; }
                    while (true) {
                        if (kidx < cntIn) { nexti = s_list[insel][kidx]; kidx++; break; }
                        if (sweep == 0) {
                            sweep = 1;
                            int tmp = insel; insel = outsel; outsel = tmp;
                            cntIn = cntOut; cntOut = 0; kidx = 0;
                            __syncthreads();   // t0's list writes -> visible
                            continue;
                        }
                        break;
                    }
                }
                if (nexti >= 0 && iters >= ARR_CAP) {   // safety dump (uniform count)
                    if (t == 0) {
                        int o = cntOut;
                        s_list[outsel][o++] = nexti;
                        for (int q = kidx; q < cntIn; q++) s_list[outsel][o++] = s_list[insel][q];
                    }
                    cntOut += 1 + (cntIn - kidx);
                    nexti = -1;
                }
                if (nexti < 0) { fsel = outsel; fcnt = cntOut; break; }
                i = nexti;
                if (fromDisp) cc = ccD;
                else          cc = *(const longlong2*)&g_icost[i * N + c0];
            }
        }
    }
    __syncthreads();                       // s_p / s_list writes visible

    // Rebuild row duals from matched edges; free rows get u = 0.
    s_u[c0] = 0; s_u[c1] = 0;
    __syncthreads();
    {
        int r0 = s_p[c0]; if (r0 >= 0) s_u[r0] = g_icost[r0 * N + c0] - v0;
        int r1 = s_p[c1]; if (r1 >= 0) s_u[r1] = g_icost[r1 * N + c1] - v1;
    }
    __syncthreads();

    // ---------------------------------------------------------------
    // Phase 1d: shortest augmenting paths, int64 absolute distances.
    // Per step: 1 barrier; shipped u; speculative 8-candidate loads;
    // PLUS register cache of the previous step's 8 candidate rows
    // (col->row map frozen per search => cached data stays valid).
    // Hit check is block-uniform => uniform branch, no load wait on hit.
    // ---------------------------------------------------------------
    for (int f = 0; f < fcnt; f++) {
        const int iFree = s_list[fsel][f];

        ll   dk0 = LL_INF, dk1 = LL_INF;    // absolute dists
        int  way0 = -1, way1 = -1;
        bool used0 = false, used1 = false;
        const int p0 = s_p[c0], p1 = s_p[c1];        // frozen during search
        const ll  up0 = (p0 >= 0) ? s_u[p0] : 0;
        const ll  up1 = (p1 >= 0) ? s_u[p1] : 0;
        const ull pay0 = ((ull)(unsigned)(p0 + 1) << 32) | (unsigned)c0;
        const ull pay1 = ((ull)(unsigned)(p1 + 1) << 32) | (unsigned)c1;

        int       pcol[NW];                  // prev-step candidate cols
        longlong2 pcc[NW];                   // prev-step candidate row data
        #pragma unroll
        for (int m = 0; m < NW; m++) { pcol[m] = -1; pcc[m] = make_longlong2(0, 0); }

        int  j0 = -1;
        ll   q  = s_u[iFree];               // q = u[i0] - dist[j0]; dist=0 at root
        ll   distF;
        longlong2 cc = *(const longlong2*)&g_icost[iFree * N + c0];

        while (true) {
            if (!used0) {
                ll cand = (cc.x - v0) - q;
                if (cand < dk0) { dk0 = cand; way0 = j0; }
            }
            if (!used1) {
                ll cand = (cc.y - v1) - q;
                if (cand < dk1) { dk1 = cand; way1 = j0; }
            }
            ll k0 = used0 ? LL_INF : dk0;
            ll k1 = used1 ? LL_INF : dk1;
            ll kl; ull pl; ll ul;
            if (k1 < k0) { kl = k1; pl = pay1; ul = up1; }
            else         { kl = k0; pl = pay0; ul = up0; }

            // warp argmin on biased key; winner lane publishes (key,pay,u)
            ull bkey = bias(kl);
            unsigned hi  = (unsigned)(bkey >> 32);
            unsigned lo  = (unsigned)bkey;
            unsigned whi = __reduce_min_sync(FULLMASK, hi);
            unsigned wlo = __reduce_min_sync(FULLMASK, (hi == whi) ? lo : 0xffffffffu);
            unsigned msk = __ballot_sync(FULLMASK, (hi == whi) && (lo == wlo));
            if (lane == __ffs(msk) - 1) {
                s_slots[pb][w] = make_ulonglong2(bkey, pl);
                s_uslt[pb][w]  = ul;
            }
            __syncthreads();                // the ONLY barrier per step

            // read slots; save candidate cols; issue speculative loads
            ull  kk[NW]; ull pp[NW]; ll uu[NW]; int ncol[NW];
            #pragma unroll
            for (int m = 0; m < NW; m++) {
                ulonglong2 s = s_slots[pb][m];
                kk[m] = s.x; pp[m] = s.y;
                ncol[m] = (int)(unsigned)s.y;
            }
            {
                longlong2* usl = (longlong2*)s_uslt[pb];
                #pragma unroll
                for (int m = 0; m < NW / 2; m++) {
                    longlong2 uv = usl[m];
                    uu[2 * m] = uv.x; uu[2 * m + 1] = uv.y;
                }
            }
            longlong2 r[NW];
            #pragma unroll
            for (int m = 0; m < NW; m++) {
                int pm = (int)(unsigned)(pp[m] >> 32) - 1;
                int pr = (pm >= 0) ? pm : 0;
                r[m] = *(const longlong2*)&g_icost[pr * N + c0];
            }
            pb ^= 1;

            // tree over 8 (key, pay, u)
            #pragma unroll
            for (int s = NW / 2; s > 0; s >>= 1)
                #pragma unroll
                for (int m = 0; m < s; m++)
                    if (kk[m + s] < kk[m]) { kk[m] = kk[m + s]; pp[m] = pp[m + s]; uu[m] = uu[m + s]; }

            const ll  dJ  = unbias(kk[0]);
            const int j1  = (int)(unsigned)pp[0];
            const int pj1 = (int)(unsigned)(pp[0] >> 32) - 1;

            if      (j1 == c0) { used0 = true; s_way[c0] = way0; }
            else if (j1 == c1) { used1 = true; s_way[c1] = way1; }
            j0 = j1;
            if (pj1 < 0) { distF = dJ; break; }    // reached a free column

            q = uu[0] - dJ;

            // cache hit check (all values uniform -> uniform branch)
            bool hit = false; longlong2 hcc = make_longlong2(0, 0);
            #pragma unroll
            for (int m = 0; m < NW; m++)
                if (pcol[m] == j1) { hit = true; hcc = pcc[m]; }
            if (hit) {
                cc = hcc;                   // no dependency on in-flight r[]
            } else {
                const int wi = j1 >> 6;     // winner warp
                longlong2 sel = r[0];
                #pragma unroll
                for (int m = 1; m < NW; m++)
                    if (wi == m) sel = r[m];
                cc = sel;
            }
            // rotate cache (r[] waits overlap the next barrier)
            #pragma unroll
            for (int m = 0; m < NW; m++) { pcol[m] = ncol[m]; pcc[m] = r[m]; }
        }
        __syncthreads();                   // s_way complete; pre-augment snapshot

        // deferred dual updates (exact int adds)
        if (used0) {
            ll dd = distF - dk0;
            v0 -= dd;
            if (p0 >= 0) s_u[p0] += dd;
        }
        if (used1) {
            ll dd = distF - dk1;
            v1 -= dd;
            if (p1 >= 0) s_u[p1] += dd;
        }
        if (t == 0) s_u[iFree] += distF;
        __syncthreads();                   // duals done before p changes

        if (t == 0) {                      // augment along parent chain
            int jc = j0;
            while (true) {
                int jp = s_way[jc];
                s_p[jc] = (jp < 0) ? iFree : s_p[jp];
                if (jp < 0) break;
                jc = jp;
            }
        }
        __syncthreads();
    }

    // ---------------------------------------------------------------
    // Phase 2: loss = 0.5 * sum_j || dgm[p[j]] - dgm_x[j] ||^2 (fp64)
    // ---------------------------------------------------------------
    {
        const int r0 = s_p[c0], r1 = s_p[c1];
        double db = (double)dgm[2 * r0]     - (double)dgm_x[2 * c0];
        double dd = (double)dgm[2 * r0 + 1] - (double)dgm_x[2 * c0 + 1];
        double acc = db * db + dd * dd;
        db = (double)dgm[2 * r1]     - (double)dgm_x[2 * c1];
        dd = (double)dgm[2 * r1 + 1] - (double)dgm_x[2 * c1 + 1];
        acc += db * db + dd * dd;

        #pragma unroll
        for (int off = 16; off > 0; off >>= 1)
            acc += __shfl_down_sync(FULLMASK, acc, off);
        if (lane == 0) s_red[w] = acc;
        __syncthreads();
        if (t < NW) {
            acc = s_red[t];
            #pragma unroll
            for (int off = NW / 2; off > 0; off >>= 1)
                acc += __shfl_down_sync(0x000000ffu, acc, off);
            if (t == 0) out[0] = (float)(0.5 * acc);
        }
    }
}

extern "C" void kernel_launch(void* const* d_in, const int* in_sizes, int n_in,
                              void* d_out, int out_size)
{
    const float* dgm   = (const float*)d_in[0];
    const float* dgm_x = (const float*)d_in[1];
    float* out = (float*)d_out;
    tofu_lap_kernel<<<1, NT>>>(dgm, dgm_x, out);
}

// round 11
// speedup vs baseline: 1.0394x; 1.0394x over previous
#include <cuda_runtime.h>
#include <math_constants.h>

#define N   512
#define NT  256
#define NW  (NT / 32)
#define FULLMASK 0xffffffffu
#define ARR_CAP (3 * N)

typedef long long ll;
typedef unsigned long long ull;

#define LL_INF 0x7fffffffffffffffLL
#define SIGNF  0x8000000000000000ULL
// 2^50 fixed-point scale: total quantization error << optimum uniqueness margin.
#define SCALE_D 1125899906842624.0

// 512x512 int64 cost matrix (2 MB) — static device scratch (no allocs).
__device__ ll g_icost[N * N];

__device__ __forceinline__ ull bias(ll x) { return (ull)x ^ SIGNF; }
__device__ __forceinline__ ll  unbias(ull k) { return (ll)(k ^ SIGNF); }

// Quantized Euclidean cost from squared distance. Fast sqrt: rsqrtf seed +
// 2 double NR iterations (~2^-49 rel err; tolerance is ~2^-40 abs). Guard
// keeps tiny/zero ss exact-enough and NaN-free.
__device__ __forceinline__ ll qcost(double ss) {
    if (ss < 1e-22) return 0;
    double r = (double)rsqrtf((float)ss);
    double h = 0.5 * ss;
    r = r * (1.5 - h * r * r);
    r = r * (1.5 - h * r * r);
    return __double2ll_rn(ss * r * SCALE_D);
}

// Block-wide exact (min int64 key, payload). All NT threads call, uniform.
// One __syncthreads inside; caller double-buffers `slots`.
__device__ __forceinline__ void block_argmin(ll key, ull payload, ulonglong2* slots,
                                             ll& bk, ull& bpay)
{
    const int lane = threadIdx.x & 31;
    const int w    = threadIdx.x >> 5;
    ull bkey = bias(key);
    unsigned hi  = (unsigned)(bkey >> 32);
    unsigned lo  = (unsigned)bkey;
    unsigned whi = __reduce_min_sync(FULLMASK, hi);
    unsigned wlo = __reduce_min_sync(FULLMASK, (hi == whi) ? lo : 0xffffffffu);
    unsigned msk = __ballot_sync(FULLMASK, (hi == whi) && (lo == wlo));
    if (lane == __ffs(msk) - 1)
        slots[w] = make_ulonglong2(bkey, payload);
    __syncthreads();
    ulonglong2 a0 = slots[0], a1 = slots[1], a2 = slots[2], a3 = slots[3];
    ulonglong2 a4 = slots[4], a5 = slots[5], a6 = slots[6], a7 = slots[7];
    if (a4.x < a0.x) a0 = a4;
    if (a5.x < a1.x) a1 = a5;
    if (a6.x < a2.x) a2 = a6;
    if (a7.x < a3.x) a3 = a7;
    if (a2.x < a0.x) a0 = a2;
    if (a3.x < a1.x) a1 = a3;
    if (a1.x < a0.x) a0 = a1;
    bk   = unbias(a0.x);
    bpay = a0.y;
}

__global__ void __launch_bounds__(NT, 1)
tofu_lap_kernel(const float* __restrict__ dgm,
                const float* __restrict__ dgm_x,
                float* __restrict__ out)
{
    const int t  = threadIdx.x;       // owns columns c0 = 2t, c1 = 2t+1
    const int c0 = 2 * t, c1 = 2 * t + 1;
    const int w  = t >> 5;
    const int lane = t & 31;

    __shared__ ll         s_u[N];          // row duals (int64)
    __shared__ int        s_p[N];          // col -> matched row, -1 if free
    __shared__ int        s_way[N];        // Dijkstra parents (temp: CR row flags)
    __shared__ int        s_xrow[N];       // row -> matched col, -1 (for RT)
    __shared__ int        s_argmin[N];
    __shared__ int        s_list[2][N];    // ARR ping-pong / final free-row list
    __shared__ ulonglong2 s_slots[2][NW];  // (biased key, payload) double-buffered
    __shared__ ll         s_uslt[2][NW];   // shipped u of candidate
    __shared__ double     s_red[NW];

    // ---------------------------------------------------------------
    // Phase 0 (+ fused column reduction): int64 cost matrix and
    // per-column min/argmin in one pass. FMA/fast-sqrt allowed: the
    // fixed-point tolerance (abs err << margin) covers it.
    // ---------------------------------------------------------------
    ll v0, v1;
    {
        const double xb0 = (double)dgm_x[2 * c0], xd0 = (double)dgm_x[2 * c0 + 1];
        const double xb1 = (double)dgm_x[2 * c1], xd1 = (double)dgm_x[2 * c1 + 1];
        ll vm0 = LL_INF, vm1 = LL_INF;
        int a0 = 0, a1 = 0;
        for (int i = 0; i < N; i++) {
            const double b = (double)dgm[2 * i], d = (double)dgm[2 * i + 1];
            double db0 = b - xb0, dd0 = d - xd0;
            double db1 = b - xb1, dd1 = d - xd1;
            longlong2 cc;
            cc.x = qcost(db0 * db0 + dd0 * dd0);
            cc.y = qcost(db1 * db1 + dd1 * dd1);
            *(longlong2*)&g_icost[i * N + c0] = cc;
            if (cc.x < vm0) { vm0 = cc.x; a0 = i; }
            if (cc.y < vm1) { vm1 = cc.y; a1 = i; }
        }
        v0 = vm0; v1 = vm1;
        s_argmin[c0] = a0; s_argmin[c1] = a1;
        s_way[c0] = 0; s_way[c1] = 0;      // temp: row-claimed flags for CR
    }
    __syncthreads();

    // Greedy pre-match of unique argmin rows (tight, feasible).
    if (t == 0) {
        int cnt = 0;
        for (int i = 0; i < N; i++) s_xrow[i] = -1;
        for (int jj = 0; jj < N; jj++) {
            int r = s_argmin[jj];
            if (!s_way[r]) { s_way[r] = 1; s_p[jj] = r; s_xrow[r] = jj; }
            else           { s_p[jj] = -1; }
        }
        for (int i = 0; i < N; i++)
            if (!s_way[i]) s_list[0][cnt++] = i;
        s_argmin[0] = cnt;
    }
    __syncthreads();
    const int cnt0 = s_argmin[0];

    int pb = 0;

    // ---------------------------------------------------------------
    // Phase 1b: reduction transfer. v[j1] -= min_{j!=j1}(c[i][j]-v[j])
    // for each CR-matched row. Next-row prefetch (addresses known).
    // ---------------------------------------------------------------
    {
        longlong2 ccn = *(const longlong2*)&g_icost[c0];
        for (int i = 0; i < N; i++) {
            longlong2 cc = ccn;
            if (i + 1 < N) ccn = *(const longlong2*)&g_icost[(i + 1) * N + c0];
            const int j1 = s_xrow[i];      // broadcast LDS; uniform branch
            if (j1 < 0) continue;
            ll k0 = (c0 == j1) ? LL_INF : (cc.x - v0);
            ll k1 = (c1 == j1) ? LL_INF : (cc.y - v1);
            ll kl = (k1 < k0) ? k1 : k0;
            ll bk; ull bp;
            block_argmin(kl, 0, s_slots[pb], bk, bp); pb ^= 1;
            if (c0 == j1) v0 -= bk;
            if (c1 == j1) v1 -= bk;
        }
    }
    __syncthreads();

    // ---------------------------------------------------------------
    // Phase 1c: augmenting row reduction. Driver state fully replicated
    // across threads (uniform); only s_p / s_list writes are t0's.
    // ---------------------------------------------------------------
    int fsel, fcnt;
    {
        int p0r = s_p[c0], p1r = s_p[c1];   // register mirrors of own cols
        int kidx = 1, cntIn = cnt0, cntOut = 0;
        int insel = 0, outsel = 1, sweep = 0, iters = 0;

        if (cntIn == 0) { fsel = 1; fcnt = 0; }
        else {
            int i = s_list[0][0];
            longlong2 cc = *(const longlong2*)&g_icost[i * N + c0];
            while (true) {
                ll k0 = cc.x - v0;
                ll k1 = cc.y - v1;
                ull pay0 = ((ull)(unsigned)(p0r + 1) << 32) | (unsigned)c0;
                ull pay1 = ((ull)(unsigned)(p1r + 1) << 32) | (unsigned)c1;
                ll kl; ull pl;
                if (k1 < k0) { kl = k1; pl = pay1; } else { kl = k0; pl = pay0; }
                ll kmin; ull p1u;
                block_argmin(kl, pl, s_slots[pb], kmin, p1u); pb ^= 1;
                const int j1   = (int)(unsigned)p1u;
                const int p_j1 = (int)(unsigned)(p1u >> 32) - 1;

                // speculative: displaced-row cc (used when strict && p_j1>=0)
                longlong2 ccD;
                {
                    int pr = (p_j1 >= 0) ? p_j1 : 0;
                    ccD = *(const longlong2*)&g_icost[pr * N + c0];
                }

                ll e0 = (c0 == j1) ? LL_INF : k0;
                ll e1 = (c1 == j1) ? LL_INF : k1;
                if (e1 < e0) { kl = e1; pl = pay1; } else { kl = e0; pl = pay0; }
                ll ksub; ull p2u;
                block_argmin(kl, pl, s_slots[pb], ksub, p2u); pb ^= 1;
                const int j2   = (int)(unsigned)p2u;
                const int p_j2 = (int)(unsigned)(p2u >> 32) - 1;

                const bool strict = (kmin < ksub);
                if (strict) {
                    ll dv = ksub - kmin;
                    if      (j1 == c0) v0 -= dv;
                    else if (j1 == c1) v1 -= dv;
                }
                // uniform driver
                int jf = j1, i0;
                if (!strict && p_j1 >= 0) { jf = j2; i0 = p_j2; }
                else                      { i0 = p_j1; }
                if (t == 0) s_p[jf] = i;
                if (jf == c0) p0r = i;
                if (jf == c1) p1r = i;
                iters++;

                int nexti = -1;
                bool fromDisp = false;
                if (i0 >= 0 && strict) { nexti = i0; fromDisp = true; }
                else {
                    if (i0 >= 0) { if (t == 0) s_list[outsel][cntOut] = i0; cntOut++; }
                    while (true) {
                        if (kidx < cntIn) { nexti = s_list[insel][kidx]; kidx++; break; }
                        if (sweep == 0) {
                            sweep = 1;
                            int tmp = insel; insel = outsel; outsel = tmp;
                            cntIn = cntOut; cntOut = 0; kidx = 0;
                            __syncthreads();   // t0's list writes -> visible
                            continue;
                        }
                        break;
                    }
                }
                if (nexti >= 0 && iters >= ARR_CAP) {   // safety dump (uniform count)
                    if (t == 0) {
                        int o = cntOut;
                        s_list[outsel][o++] = nexti;
                        for (int q = kidx; q < cntIn; q++) s_list[outsel][o++] = s_list[insel][q];
                    }
                    cntOut += 1 + (cntIn - kidx);
                    nexti = -1;
                }
                if (nexti < 0) { fsel = outsel; fcnt = cntOut; break; }
                i = nexti;
                if (fromDisp) cc = ccD;
                else          cc = *(const longlong2*)&g_icost[i * N + c0];
            }
        }
    }
    __syncthreads();                       // s_p / s_list writes visible

    // Rebuild row duals from matched edges; free rows get u = 0.
    s_u[c0] = 0; s_u[c1] = 0;
    __syncthreads();
    {
        int r0 = s_p[c0]; if (r0 >= 0) s_u[r0] = g_icost[r0 * N + c0] - v0;
        int r1 = s_p[c1]; if (r1 >= 0) s_u[r1] = g_icost[r1 * N + c1] - v1;
    }
    __syncthreads();

    // ---------------------------------------------------------------
    // Phase 1d: shortest augmenting paths, int64 absolute distances.
    // Per step: 1 barrier; candidate u shipped in slots; speculative
    // prefetch of all 8 warp-candidate rows; winner row by reg select.
    // (R9 inner loop — loser-row cache removed: it added ~25 instrs/step
    // for no removed stall and regressed R10.)
    // ---------------------------------------------------------------
    for (int f = 0; f < fcnt; f++) {
        const int iFree = s_list[fsel][f];

        ll   dk0 = LL_INF, dk1 = LL_INF;    // absolute dists
        int  way0 = -1, way1 = -1;
        bool used0 = false, used1 = false;
        const int p0 = s_p[c0], p1 = s_p[c1];        // frozen during search
        const ll  up0 = (p0 >= 0) ? s_u[p0] : 0;
        const ll  up1 = (p1 >= 0) ? s_u[p1] : 0;
        const ull pay0 = ((ull)(unsigned)(p0 + 1) << 32) | (unsigned)c0;
        const ull pay1 = ((ull)(unsigned)(p1 + 1) << 32) | (unsigned)c1;

        int  j0 = -1;
        ll   q  = s_u[iFree];               // q = u[i0] - dist[j0]; dist=0 at root
        ll   distF;
        longlong2 cc = *(const longlong2*)&g_icost[iFree * N + c0];

        while (true) {
            if (!used0) {
                ll cand = (cc.x - v0) - q;
                if (cand < dk0) { dk0 = cand; way0 = j0; }
            }
            if (!used1) {
                ll cand = (cc.y - v1) - q;
                if (cand < dk1) { dk1 = cand; way1 = j0; }
            }
            ll k0 = used0 ? LL_INF : dk0;
            ll k1 = used1 ? LL_INF : dk1;
            ll kl; ull pl; ll ul;
            if (k1 < k0) { kl = k1; pl = pay1; ul = up1; }
            else         { kl = k0; pl = pay0; ul = up0; }

            // warp argmin on biased key; winner lane publishes (key,pay,u)
            ull bkey = bias(kl);
            unsigned hi  = (unsigned)(bkey >> 32);
            unsigned lo  = (unsigned)bkey;
            unsigned whi = __reduce_min_sync(FULLMASK, hi);
            unsigned wlo = __reduce_min_sync(FULLMASK, (hi == whi) ? lo : 0xffffffffu);
            unsigned msk = __ballot_sync(FULLMASK, (hi == whi) && (lo == wlo));
            if (lane == __ffs(msk) - 1) {
                s_slots[pb][w] = make_ulonglong2(bkey, pl);
                s_uslt[pb][w]  = ul;
            }
            __syncthreads();                // the ONLY barrier per step

            // read slots; immediately issue speculative loads for all 8
            ull  kk[NW]; ull pp[NW]; ll uu[NW];
            #pragma unroll
            for (int m = 0; m < NW; m++) {
                ulonglong2 s = s_slots[pb][m];
                kk[m] = s.x; pp[m] = s.y;
            }
            {
                longlong2* usl = (longlong2*)s_uslt[pb];
                #pragma unroll
                for (int m = 0; m < NW / 2; m++) {
                    longlong2 uv = usl[m];
                    uu[2 * m] = uv.x; uu[2 * m + 1] = uv.y;
                }
            }
            longlong2 r[NW];
            #pragma unroll
            for (int m = 0; m < NW; m++) {
                int pm = (int)(unsigned)(pp[m] >> 32) - 1;
                int pr = (pm >= 0) ? pm : 0;
                r[m] = *(const longlong2*)&g_icost[pr * N + c0];
            }
            pb ^= 1;

            // tree over 8 (key, pay, u)
            #pragma unroll
            for (int s = NW / 2; s > 0; s >>= 1)
                #pragma unroll
                for (int m = 0; m < s; m++)
                    if (kk[m + s] < kk[m]) { kk[m] = kk[m + s]; pp[m] = pp[m + s]; uu[m] = uu[m + s]; }

            const ll  dJ  = unbias(kk[0]);
            const int j1  = (int)(unsigned)pp[0];
            const int pj1 = (int)(unsigned)(pp[0] >> 32) - 1;

            if      (j1 == c0) { used0 = true; s_way[c0] = way0; }
            else if (j1 == c1) { used1 = true; s_way[c1] = way1; }
            j0 = j1;
            if (pj1 < 0) { distF = dJ; break; }    // reached a free column

            q = uu[0] - dJ;
            const int wi = j1 >> 6;                // winner warp
            longlong2 sel = r[0];
            #pragma unroll
            for (int m = 1; m < NW; m++)
                if (wi == m) sel = r[m];
            cc = sel;
        }
        __syncthreads();                   // s_way complete; pre-augment snapshot

        // deferred dual updates (exact int adds)
        if (used0) {
            ll dd = distF - dk0;
            v0 -= dd;
            if (p0 >= 0) s_u[p0] += dd;
        }
        if (used1) {
            ll dd = distF - dk1;
            v1 -= dd;
            if (p1 >= 0) s_u[p1] += dd;
        }
        if (t == 0) s_u[iFree] += distF;
        __syncthreads();                   // duals done before p changes

        if (t == 0) {                      // augment along parent chain
            int jc = j0;
            while (true) {
                int jp = s_way[jc];
                s_p[jc] = (jp < 0) ? iFree : s_p[jp];
                if (jp < 0) break;
                jc = jp;
            }
        }
        __syncthreads();
    }

    // ---------------------------------------------------------------
    // Phase 2: loss = 0.5 * sum_j || dgm[p[j]] - dgm_x[j] ||^2 (fp64)
    // ---------------------------------------------------------------
    {
        const int r0 = s_p[c0], r1 = s_p[c1];
        double db = (double)dgm[2 * r0]     - (double)dgm_x[2 * c0];
        double dd = (double)dgm[2 * r0 + 1] - (double)dgm_x[2 * c0 + 1];
        double acc = db * db + dd * dd;
        db = (double)dgm[2 * r1]     - (double)dgm_x[2 * c1];
        dd = (double)dgm[2 * r1 + 1] - (double)dgm_x[2 * c1 + 1];
        acc += db * db + dd * dd;

        #pragma unroll
        for (int off = 16; off > 0; off >>= 1)
            acc += __shfl_down_sync(FULLMASK, acc, off);
        if (lane == 0) s_red[w] = acc;
        __syncthreads();
        if (t < NW) {
            acc = s_red[t];
            #pragma unroll
            for (int off = NW / 2; off > 0; off >>= 1)
                acc += __shfl_down_sync(0x000000ffu, acc, off);
            if (t == 0) out[0] = (float)(0.5 * acc);
        }
    }
}

extern "C" void kernel_launch(void* const* d_in, const int* in_sizes, int n_in,
                              void* d_out, int out_size)
{
    const float* dgm   = (const float*)d_in[0];
    const float* dgm_x = (const float*)d_in[1];
    float* out = (float*)d_out;
    tofu_lap_kernel<<<1, NT>>>(dgm, dgm_x, out);
}

// round 12
// speedup vs baseline: 1.0942x; 1.0527x over previous
#include <cuda_runtime.h>
#include <math_constants.h>

#define N   512
#define NT  256
#define NW  (NT / 32)
#define FULLMASK 0xffffffffu
#define ARR_CAP (3 * N)

typedef long long ll;
typedef unsigned long long ull;

#define LL_INF 0x7fffffffffffffffLL
#define SIGNF  0x8000000000000000ULL
// 2^50 fixed-point scale: quantization 2^-51 per entry << optimum margin.
#define SCALE_D 1125899906842624.0

// 512x512 int64 cost matrix (2 MB) — static device scratch (no allocs).
__device__ ll g_icost[N * N];

__device__ __forceinline__ ull bias(ll x) { return (ull)x ^ SIGNF; }
__device__ __forceinline__ ll  unbias(ull k) { return (ll)(k ^ SIGNF); }

// Warp-exact writer-election for the min key: REDUX(hi) + ballot fast path;
// lo-REDUX only on the rare hi32 tie (warp-uniform branch). Returns true on
// the single lane that must publish.
__device__ __forceinline__ bool warp_min_writer(ull bkey, int lane) {
    unsigned hi  = (unsigned)(bkey >> 32);
    unsigned lo  = (unsigned)bkey;
    unsigned whi = __reduce_min_sync(FULLMASK, hi);
    bool cand = (hi == whi);
    unsigned msk = __ballot_sync(FULLMASK, cand);
    if (__popc(msk) > 1) {
        unsigned wlo = __reduce_min_sync(FULLMASK, cand ? lo : 0xffffffffu);
        msk = __ballot_sync(FULLMASK, cand && (lo == wlo));
    }
    return lane == __ffs(msk) - 1;
}

// Block-wide exact (min int64 key, payload). All NT threads call, uniform.
// One __syncthreads inside; caller double-buffers `slots`.
__device__ __forceinline__ void block_argmin(ll key, ull payload, ulonglong2* slots,
                                             ll& bk, ull& bpay)
{
    const int lane = threadIdx.x & 31;
    const int w    = threadIdx.x >> 5;
    ull bkey = bias(key);
    if (warp_min_writer(bkey, lane))
        slots[w] = make_ulonglong2(bkey, payload);
    __syncthreads();
    ulonglong2 a0 = slots[0], a1 = slots[1], a2 = slots[2], a3 = slots[3];
    ulonglong2 a4 = slots[4], a5 = slots[5], a6 = slots[6], a7 = slots[7];
    if (a4.x < a0.x) a0 = a4;
    if (a5.x < a1.x) a1 = a5;
    if (a6.x < a2.x) a2 = a6;
    if (a7.x < a3.x) a3 = a7;
    if (a2.x < a0.x) a0 = a2;
    if (a3.x < a1.x) a1 = a3;
    if (a1.x < a0.x) a0 = a1;
    bk   = unbias(a0.x);
    bpay = a0.y;
}

__global__ void __launch_bounds__(NT, 1)
tofu_lap_kernel(const float* __restrict__ dgm,
                const float* __restrict__ dgm_x,
                float* __restrict__ out)
{
    const int t  = threadIdx.x;       // owns columns c0 = 2t, c1 = 2t+1
    const int c0 = 2 * t, c1 = 2 * t + 1;
    const int w  = t >> 5;
    const int lane = t & 31;

    __shared__ ll         s_u[N];          // row duals (int64)
    __shared__ int        s_p[N];          // col -> matched row, -1 if free
    __shared__ int        s_way[N];        // Dijkstra parents (temp: CR row flags)
    __shared__ int        s_xrow[N];       // row -> matched col, -1 (for RT)
    __shared__ int        s_argmin[N];
    __shared__ int        s_list[2][N];    // ARR ping-pong / final free-row list
    __shared__ ulonglong2 s_slots[2][NW];  // (biased key, payload) double-buffered
    __shared__ ll         s_uslt[2][NW];   // shipped u of candidate
    __shared__ double     s_red[NW];

    // ---------------------------------------------------------------
    // Phase 0: fp64 cost (numpy-faithful: plain mul/add, IEEE sqrt),
    // then exact-enough fixed-point quantization to int64.
    // ---------------------------------------------------------------
    {
        const double xb0 = (double)dgm_x[2 * c0], xd0 = (double)dgm_x[2 * c0 + 1];
        const double xb1 = (double)dgm_x[2 * c1], xd1 = (double)dgm_x[2 * c1 + 1];
        for (int i = 0; i < N; i++) {
            const double b = (double)dgm[2 * i], d = (double)dgm[2 * i + 1];
            double db0 = __dsub_rn(b, xb0), dd0 = __dsub_rn(d, xd0);
            double db1 = __dsub_rn(b, xb1), dd1 = __dsub_rn(d, xd1);
            double e0 = sqrt(__dadd_rn(__dmul_rn(db0, db0), __dmul_rn(dd0, dd0)));
            double e1 = sqrt(__dadd_rn(__dmul_rn(db1, db1), __dmul_rn(dd1, dd1)));
            longlong2 cc;
            cc.x = __double2ll_rn(e0 * SCALE_D);
            cc.y = __double2ll_rn(e1 * SCALE_D);
            *(longlong2*)&g_icost[i * N + c0] = cc;
        }
        s_way[c0] = 0; s_way[c1] = 0;      // temp: row-claimed flags for CR
    }
    __syncthreads();

    // ---------------------------------------------------------------
    // Phase 1a: column reduction (int64). v[j] in registers.
    // ---------------------------------------------------------------
    ll v0, v1;
    {
        longlong2 vm = *(const longlong2*)&g_icost[c0];
        int a0 = 0, a1 = 0;
        for (int i = 1; i < N; i++) {
            longlong2 cc = *(const longlong2*)&g_icost[i * N + c0];
            if (cc.x < vm.x) { vm.x = cc.x; a0 = i; }
            if (cc.y < vm.y) { vm.y = cc.y; a1 = i; }
        }
        v0 = vm.x; v1 = vm.y;
        s_argmin[c0] = a0; s_argmin[c1] = a1;
    }
    __syncthreads();
    if (t == 0) {
        int cnt = 0;
        for (int i = 0; i < N; i++) s_xrow[i] = -1;
        for (int jj = 0; jj < N; jj++) {
            int r = s_argmin[jj];
            if (!s_way[r]) { s_way[r] = 1; s_p[jj] = r; s_xrow[r] = jj; }
            else           { s_p[jj] = -1; }
        }
        for (int i = 0; i < N; i++)
            if (!s_way[i]) s_list[0][cnt++] = i;
        s_argmin[0] = cnt;
    }
    __syncthreads();
    const int cnt0 = s_argmin[0];

    int pb = 0;

    // ---------------------------------------------------------------
    // Phase 1b: reduction transfer. v[j1] -= min_{j!=j1}(c[i][j]-v[j])
    // for each CR-matched row. Next-row prefetch (addresses known).
    // ---------------------------------------------------------------
    {
        longlong2 ccn = *(const longlong2*)&g_icost[c0];
        for (int i = 0; i < N; i++) {
            longlong2 cc = ccn;
            if (i + 1 < N) ccn = *(const longlong2*)&g_icost[(i + 1) * N + c0];
            const int j1 = s_xrow[i];      // broadcast LDS; uniform branch
            if (j1 < 0) continue;
            ll k0 = (c0 == j1) ? LL_INF : (cc.x - v0);
            ll k1 = (c1 == j1) ? LL_INF : (cc.y - v1);
            ll kl = (k1 < k0) ? k1 : k0;
            ll bk; ull bp;
            block_argmin(kl, 0, s_slots[pb], bk, bp); pb ^= 1;
            if (c0 == j1) v0 -= bk;
            if (c1 == j1) v1 -= bk;
        }
    }
    __syncthreads();

    // ---------------------------------------------------------------
    // Phase 1c: augmenting row reduction. Driver state fully replicated
    // across threads (uniform); only s_p / s_list writes are t0's.
    // ---------------------------------------------------------------
    int fsel, fcnt;
    {
        int p0r = s_p[c0], p1r = s_p[c1];   // register mirrors of own cols
        int kidx = 1, cntIn = cnt0, cntOut = 0;
        int insel = 0, outsel = 1, sweep = 0, iters = 0;

        if (cntIn == 0) { fsel = 1; fcnt = 0; }
        else {
            int i = s_list[0][0];
            longlong2 cc = *(const longlong2*)&g_icost[i * N + c0];
            while (true) {
                ll k0 = cc.x - v0;
                ll k1 = cc.y - v1;
                ull pay0 = ((ull)(unsigned)(p0r + 1) << 32) | (unsigned)c0;
                ull pay1 = ((ull)(unsigned)(p1r + 1) << 32) | (unsigned)c1;
                ll kl; ull pl;
                if (k1 < k0) { kl = k1; pl = pay1; } else { kl = k0; pl = pay0; }
                ll kmin; ull p1u;
                block_argmin(kl, pl, s_slots[pb], kmin, p1u); pb ^= 1;
                const int j1   = (int)(unsigned)p1u;
                const int p_j1 = (int)(unsigned)(p1u >> 32) - 1;

                // speculative: displaced-row cc (used when strict && p_j1>=0)
                longlong2 ccD;
                {
                    int pr = (p_j1 >= 0) ? p_j1 : 0;
                    ccD = *(const longlong2*)&g_icost[pr * N + c0];
                }

                ll e0 = (c0 == j1) ? LL_INF : k0;
                ll e1 = (c1 == j1) ? LL_INF : k1;
                if (e1 < e0) { kl = e1; pl = pay1; } else { kl = e0; pl = pay0; }
                ll ksub; ull p2u;
                block_argmin(kl, pl, s_slots[pb], ksub, p2u); pb ^= 1;
                const int j2   = (int)(unsigned)p2u;
                const int p_j2 = (int)(unsigned)(p2u >> 32) - 1;

                const bool strict = (kmin < ksub);
                if (strict) {
                    ll dv = ksub - kmin;
                    if      (j1 == c0) v0 -= dv;
                    else if (j1 == c1) v1 -= dv;
                }
                // uniform driver
                int jf = j1, i0;
                if (!strict && p_j1 >= 0) { jf = j2; i0 = p_j2; }
                else                      { i0 = p_j1; }
                if (t == 0) s_p[jf] = i;
                if (jf == c0) p0r = i;
                if (jf == c1) p1r = i;
                iters++;

                int nexti = -1;
                bool fromDisp = false;
                if (i0 >= 0 && strict) { nexti = i0; fromDisp = true; }
                else {
                    if (i0 >= 0) { if (t == 0) s_list[outsel][cntOut] = i0; cntOut++; }
                    while (true) {
                        if (kidx < cntIn) { nexti = s_list[insel][kidx]; kidx++; break; }
                        if (sweep == 0) {
                            sweep = 1;
                            int tmp = insel; insel = outsel; outsel = tmp;
                            cntIn = cntOut; cntOut = 0; kidx = 0;
                            __syncthreads();   // t0's list writes -> visible
                            continue;
                        }
                        break;
                    }
                }
                if (nexti >= 0 && iters >= ARR_CAP) {   // safety dump (uniform count)
                    if (t == 0) {
                        int o = cntOut;
                        s_list[outsel][o++] = nexti;
                        for (int q = kidx; q < cntIn; q++) s_list[outsel][o++] = s_list[insel][q];
                    }
                    cntOut += 1 + (cntIn - kidx);
                    nexti = -1;
                }
                if (nexti < 0) { fsel = outsel; fcnt = cntOut; break; }
                i = nexti;
                if (fromDisp) cc = ccD;
                else          cc = *(const longlong2*)&g_icost[i * N + c0];
            }
        }
    }
    __syncthreads();                       // s_p / s_list writes visible

    // Rebuild row duals from matched edges; free rows get u = 0.
    s_u[c0] = 0; s_u[c1] = 0;
    __syncthreads();
    {
        int r0 = s_p[c0]; if (r0 >= 0) s_u[r0] = g_icost[r0 * N + c0] - v0;
        int r1 = s_p[c1]; if (r1 >= 0) s_u[r1] = g_icost[r1 * N + c1] - v1;
    }
    __syncthreads();

    // ---------------------------------------------------------------
    // Phase 1d: shortest augmenting paths, int64 absolute distances.
    // Per step: 1 barrier; candidate u shipped in slots; speculative
    // prefetch of all 8 warp-candidate rows; winner row by reg select.
    // ---------------------------------------------------------------
    for (int f = 0; f < fcnt; f++) {
        const int iFree = s_list[fsel][f];

        ll   dk0 = LL_INF, dk1 = LL_INF;    // absolute dists
        int  way0 = -1, way1 = -1;
        bool used0 = false, used1 = false;
        const int p0 = s_p[c0], p1 = s_p[c1];        // frozen during search
        const ll  up0 = (p0 >= 0) ? s_u[p0] : 0;
        const ll  up1 = (p1 >= 0) ? s_u[p1] : 0;
        const ull pay0 = ((ull)(unsigned)(p0 + 1) << 32) | (unsigned)c0;
        const ull pay1 = ((ull)(unsigned)(p1 + 1) << 32) | (unsigned)c1;

        int  j0 = -1;
        ll   q  = s_u[iFree];               // q = u[i0] - dist[j0]; dist=0 at root
        ll   distF;
        longlong2 cc = *(const longlong2*)&g_icost[iFree * N + c0];

        while (true) {
            if (!used0) {
                ll cand = (cc.x - v0) - q;
                if (cand < dk0) { dk0 = cand; way0 = j0; }
            }
            if (!used1) {
                ll cand = (cc.y - v1) - q;
                if (cand < dk1) { dk1 = cand; way1 = j0; }
            }
            ll k0 = used0 ? LL_INF : dk0;
            ll k1 = used1 ? LL_INF : dk1;
            ll kl; ull pl; ll ul;
            if (k1 < k0) { kl = k1; pl = pay1; ul = up1; }
            else         { kl = k0; pl = pay0; ul = up0; }

            // warp argmin: fast writer election (hi REDUX + ballot; lo path rare)
            ull bkey = bias(kl);
            if (warp_min_writer(bkey, lane)) {
                s_slots[pb][w] = make_ulonglong2(bkey, pl);
                s_uslt[pb][w]  = ul;
            }
            __syncthreads();                // the ONLY barrier per step

            // read slots; immediately issue speculative loads for all 8
            ull  kk[NW]; ull pp[NW]; ll uu[NW];
            #pragma unroll
            for (int m = 0; m < NW; m++) {
                ulonglong2 s = s_slots[pb][m];
                kk[m] = s.x; pp[m] = s.y;
            }
            {
                longlong2* usl = (longlong2*)s_uslt[pb];
                #pragma unroll
                for (int m = 0; m < NW / 2; m++) {
                    longlong2 uv = usl[m];
                    uu[2 * m] = uv.x; uu[2 * m + 1] = uv.y;
                }
            }
            longlong2 r[NW];
            #pragma unroll
            for (int m = 0; m < NW; m++) {
                int pm = (int)(unsigned)(pp[m] >> 32) - 1;
                int pr = (pm >= 0) ? pm : 0;
                r[m] = *(const longlong2*)&g_icost[pr * N + c0];
            }
            pb ^= 1;

            // tree over 8 (key, pay, u)
            #pragma unroll
            for (int s = NW / 2; s > 0; s >>= 1)
                #pragma unroll
                for (int m = 0; m < s; m++)
                    if (kk[m + s] < kk[m]) { kk[m] = kk[m + s]; pp[m] = pp[m + s]; uu[m] = uu[m + s]; }

            const ll  dJ  = unbias(kk[0]);
            const int j1  = (int)(unsigned)pp[0];
            const int pj1 = (int)(unsigned)(pp[0] >> 32) - 1;

            if      (j1 == c0) { used0 = true; s_way[c0] = way0; }
            else if (j1 == c1) { used1 = true; s_way[c1] = way1; }
            j0 = j1;
            if (pj1 < 0) { distF = dJ; break; }    // reached a free column

            q = uu[0] - dJ;
            const int wi = j1 >> 6;                // winner warp
            longlong2 sel = r[0];
            #pragma unroll
            for (int m = 1; m < NW; m++)
                if (wi == m) sel = r[m];
            cc = sel;
        }
        __syncthreads();                   // s_way complete; pre-augment snapshot

        // deferred dual updates (exact int adds)
        if (used0) {
            ll dd = distF - dk0;
            v0 -= dd;
            if (p0 >= 0) s_u[p0] += dd;
        }
        if (used1) {
            ll dd = distF - dk1;
            v1 -= dd;
            if (p1 >= 0) s_u[p1] += dd;
        }
        if (t == 0) s_u[iFree] += distF;
        __syncthreads();                   // duals done before p changes

        if (t == 0) {                      // augment along parent chain
            int jc = j0;
            while (true) {
                int jp = s_way[jc];
                s_p[jc] = (jp < 0) ? iFree : s_p[jp];
                if (jp < 0) break;
                jc = jp;
            }
        }
        __syncthreads();
    }

    // ---------------------------------------------------------------
    // Phase 2: loss = 0.5 * sum_j || dgm[p[j]] - dgm_x[j] ||^2 (fp64)
    // ---------------------------------------------------------------
    {
        const int r0 = s_p[c0], r1 = s_p[c1];
        double db = (double)dgm[2 * r0]     - (double)dgm_x[2 * c0];
        double dd = (double)dgm[2 * r0 + 1] - (double)dgm_x[2 * c0 + 1];
        double acc = db * db + dd * dd;
        db = (double)dgm[2 * r1]     - (double)dgm_x[2 * c1];
        dd = (double)dgm[2 * r1 + 1] - (double)dgm_x[2 * c1 + 1];
        acc += db * db + dd * dd;

        #pragma unroll
        for (int off = 16; off > 0; off >>= 1)
            acc += __shfl_down_sync(FULLMASK, acc, off);
        if (lane == 0) s_red[w] = acc;
        __syncthreads();
        if (t < NW) {
            acc = s_red[t];
            #pragma unroll
            for (int off = NW / 2; off > 0; off >>= 1)
                acc += __shfl_down_sync(0x000000ffu, acc, off);
            if (t == 0) out[0] = (float)(0.5 * acc);
        }
    }
}

extern "C" void kernel_launch(void* const* d_in, const int* in_sizes, int n_in,
                              void* d_out, int out_size)
{
    const float* dgm   = (const float*)d_in[0];
    const float* dgm_x = (const float*)d_in[1];
    float* out = (float*)d_out;
    tofu_lap_kernel<<<1, NT>>>(dgm, dgm_x, out);
}